// round 9
// baseline (speedup 1.0000x reference)
#include <cuda_runtime.h>

// PyramidROIAlign: B=2, N=1000 boxes, C=256, 7x7 pool.
// Persistent fused kernel: 1216 resident CTAs grid-stride over 16-item groups.
// Double-buffered SMEM params: threads 0..15 compute NEXT group's params while
// all 256 threads gather the CURRENT group (R6 body: 16 lanes/item, 4 epochs).

#define POOL 7
#define NPTS (POOL * POOL)
#define CCH 256
#define LANES 16
#define GROUP 16
#define PERSIST_CTAS 1216   // 152 SMs x 8 CTAs

__device__ __forceinline__ void compute_params(
    int item, int total_items, int boxes_per_batch,
    const float* __restrict__ boxes, const float* __restrict__ image_shape,
    const float* __restrict__ P2, const float* __restrict__ P3,
    const float* __restrict__ P4, const float* __restrict__ P5,
    ulonglong4* s_addr, float2* s_w, int slot)
{
    if (item >= total_items) return;
    const int bn = item / NPTS;
    const int pt = item - bn * NPTS;
    const int py = pt / POOL;
    const int px = pt - py * POOL;
    const int b  = bn / boxes_per_batch;

    const float4 bx = ((const float4*)boxes)[bn];
    const float y1 = bx.x, x1 = bx.y, y2 = bx.z, x2 = bx.w;
    const float h = y2 - y1;
    const float w = x2 - x1;

    // Level selection — exact reference fp32 op order; rintf == jnp.round.
    const float area = image_shape[0] * image_shape[1];
    float lvlf = log2f(sqrtf(h * w) / (224.0f / sqrtf(area)));
    lvlf = fminf(5.0f, fmaxf(2.0f, 4.0f + rintf(lvlf)));
    const int lvl = (int)lvlf;

    const float* fmap;
    int H;
    if (lvl == 2)      { fmap = P2; H = 256; }
    else if (lvl == 3) { fmap = P3; H = 128; }
    else if (lvl == 4) { fmap = P4; H = 64;  }
    else               { fmap = P5; H = 32;  }
    const int W = H;

    // Reference order: in_y = (y1 + h*gy) * (H-1)
    const float gy = (float)py * (1.0f / 6.0f);
    const float gx = (float)px * (1.0f / 6.0f);
    const float in_y = (y1 + h * gy) * (float)(H - 1);
    const float in_x = (x1 + w * gx) * (float)(W - 1);

    const float y0f = floorf(in_y);
    const float x0f = floorf(in_x);
    const float wy = in_y - y0f;
    const float wx = in_x - x0f;

    int y0  = min(max((int)y0f, 0), H - 1);
    int y1i = min(y0 + 1, H - 1);
    int x0  = min(max((int)x0f, 0), W - 1);
    int x1i = min(x0 + 1, W - 1);

    const unsigned long long base =
        (unsigned long long)fmap + (unsigned long long)b * H * W * CCH * 4ull;
    const unsigned long long rowT = base + (unsigned long long)(y0  * W) * (CCH * 4ull);
    const unsigned long long rowB = base + (unsigned long long)(y1i * W) * (CCH * 4ull);

    ulonglong4 a;
    a.x = rowT + (unsigned long long)x0  * (CCH * 4ull);
    a.y = rowT + (unsigned long long)x1i * (CCH * 4ull);
    a.z = rowB + (unsigned long long)x0  * (CCH * 4ull);
    a.w = rowB + (unsigned long long)x1i * (CCH * 4ull);
    s_addr[slot] = a;
    s_w[slot] = make_float2(wx, wy);
}

__global__ void __launch_bounds__(256)
roi_persist_kernel(const float* __restrict__ boxes,
                   const float* __restrict__ image_shape,
                   const float* __restrict__ P2,
                   const float* __restrict__ P3,
                   const float* __restrict__ P4,
                   const float* __restrict__ P5,
                   float* __restrict__ out,
                   int total_items, int boxes_per_batch, int num_groups)
{
    __shared__ ulonglong4 s_addr[2][GROUP];
    __shared__ float2     s_w[2][GROUP];

    const int tid = threadIdx.x;
    int g = blockIdx.x;
    if (g >= num_groups) return;

    // Prologue: params for the first group into buffer 0.
    if (tid < GROUP)
        compute_params(g * GROUP + tid, total_items, boxes_per_batch,
                       boxes, image_shape, P2, P3, P4, P5,
                       s_addr[0], s_w[0], tid);
    __syncthreads();

    int p = 0;
    const int local = tid >> 4;
    const int lane  = tid & (LANES - 1);

    while (true) {
        const int gn = g + gridDim.x;

        // Overlap: compute NEXT group's params into the other buffer.
        if (tid < GROUP && gn < num_groups)
            compute_params(gn * GROUP + tid, total_items, boxes_per_batch,
                           boxes, image_shape, P2, P3, P4, P5,
                           s_addr[p ^ 1], s_w[p ^ 1], tid);

        // Gather current group (R6 body).
        const int item = g * GROUP + local;
        if (item < total_items) {
            const ulonglong4 a = s_addr[p][local];
            const float2 wv = s_w[p][local];
            const float wx = wv.x, wy = wv.y;

            const float4* __restrict__ tl = (const float4*)a.x;
            const float4* __restrict__ tr = (const float4*)a.y;
            const float4* __restrict__ bl = (const float4*)a.z;
            const float4* __restrict__ br = (const float4*)a.w;
            float4* __restrict__ o = (float4*)(out + (size_t)item * CCH);

#pragma unroll
            for (int j = 0; j < 4; j++) {
                const int c = lane + j * LANES;
                const float4 vtl = tl[c];
                const float4 vtr = tr[c];
                const float4 vbl = bl[c];
                const float4 vbr = br[c];
                float4 r;
                float t, bt;
                t  = vtl.x + (vtr.x - vtl.x) * wx;  bt = vbl.x + (vbr.x - vbl.x) * wx;  r.x = t + (bt - t) * wy;
                t  = vtl.y + (vtr.y - vtl.y) * wx;  bt = vbl.y + (vbr.y - vbl.y) * wx;  r.y = t + (bt - t) * wy;
                t  = vtl.z + (vtr.z - vtl.z) * wx;  bt = vbl.z + (vbr.z - vbl.z) * wx;  r.z = t + (bt - t) * wy;
                t  = vtl.w + (vtr.w - vtl.w) * wx;  bt = vbl.w + (vbr.w - vbl.w) * wx;  r.w = t + (bt - t) * wy;
                o[c] = r;
            }
        }

        if (gn >= num_groups) break;
        __syncthreads();   // next buffer ready; current buffer free for reuse
        p ^= 1;
        g = gn;
    }
}

extern "C" void kernel_launch(void* const* d_in, const int* in_sizes, int n_in,
                              void* d_out, int out_size)
{
    const float* boxes = (const float*)d_in[0];
    const float* ishp  = (const float*)d_in[1];
    const float* P2    = (const float*)d_in[2];
    const float* P3    = (const float*)d_in[3];
    const float* P4    = (const float*)d_in[4];
    const float* P5    = (const float*)d_in[5];
    float* out = (float*)d_out;

    const int B = in_sizes[2] / (256 * 256 * 256);
    const int total_boxes = in_sizes[0] / 4;
    const int boxes_per_batch = total_boxes / B;
    const int total_items = total_boxes * NPTS;
    const int num_groups = (total_items + GROUP - 1) / GROUP;

    const int blocks = (num_groups < PERSIST_CTAS) ? num_groups : PERSIST_CTAS;
    roi_persist_kernel<<<blocks, 256>>>(boxes, ishp, P2, P3, P4, P5, out,
                                        total_items, boxes_per_batch, num_groups);
}

// round 10
// speedup vs baseline: 1.3210x; 1.3210x over previous
#include <cuda_runtime.h>

// PyramidROIAlign: B=2, N=1000 boxes, C=256, 7x7 pool.
// Warp-autonomous fused kernel: each warp owns 4 items. Lanes 0-3 compute the
// 4 items' params into warp-private SMEM, __syncwarp, then each half-warp
// gathers 2 items sequentially (R6 body: 16 lanes/item, unroll-4 epochs).
// No CTA barrier, no cross-warp coupling.

#define POOL 7
#define NPTS (POOL * POOL)
#define CCH 256
#define LANES 16
#define ITEMS_PER_WARP 4
#define WARPS_PER_CTA 8

__global__ void __launch_bounds__(256)
roi_warpauto_kernel(const float* __restrict__ boxes,
                    const float* __restrict__ image_shape,
                    const float* __restrict__ P2,
                    const float* __restrict__ P3,
                    const float* __restrict__ P4,
                    const float* __restrict__ P5,
                    float* __restrict__ out,
                    int total_items, int boxes_per_batch)
{
    __shared__ ulonglong4 s_addr[WARPS_PER_CTA][ITEMS_PER_WARP];
    __shared__ float2     s_w[WARPS_PER_CTA][ITEMS_PER_WARP];

    const int warp_in_cta = threadIdx.x >> 5;
    const int lane32 = threadIdx.x & 31;
    const int gwarp = blockIdx.x * WARPS_PER_CTA + warp_in_cta;
    const int wbase = gwarp * ITEMS_PER_WARP;
    if (wbase >= total_items) return;

    // ---- params: lanes 0..3 each compute one item ----
    if (lane32 < ITEMS_PER_WARP) {
        const int item = wbase + lane32;
        if (item < total_items) {
            const int bn = item / NPTS;
            const int pt = item - bn * NPTS;
            const int py = pt / POOL;
            const int px = pt - py * POOL;
            const int b  = bn / boxes_per_batch;

            const float4 bx = ((const float4*)boxes)[bn];
            const float y1 = bx.x, x1 = bx.y, y2 = bx.z, x2 = bx.w;
            const float h = y2 - y1;
            const float w = x2 - x1;

            // Level selection — exact reference fp32 op order; rintf == jnp.round.
            const float area = image_shape[0] * image_shape[1];
            float lvlf = log2f(sqrtf(h * w) / (224.0f / sqrtf(area)));
            lvlf = fminf(5.0f, fmaxf(2.0f, 4.0f + rintf(lvlf)));
            const int lvl = (int)lvlf;

            const float* fmap;
            int H;
            if (lvl == 2)      { fmap = P2; H = 256; }
            else if (lvl == 3) { fmap = P3; H = 128; }
            else if (lvl == 4) { fmap = P4; H = 64;  }
            else               { fmap = P5; H = 32;  }
            const int W = H;

            // Reference order: in_y = (y1 + h*gy) * (H-1)
            const float gy = (float)py * (1.0f / 6.0f);
            const float gx = (float)px * (1.0f / 6.0f);
            const float in_y = (y1 + h * gy) * (float)(H - 1);
            const float in_x = (x1 + w * gx) * (float)(W - 1);

            const float y0f = floorf(in_y);
            const float x0f = floorf(in_x);
            const float wy = in_y - y0f;
            const float wx = in_x - x0f;

            int y0  = min(max((int)y0f, 0), H - 1);
            int y1i = min(y0 + 1, H - 1);
            int x0  = min(max((int)x0f, 0), W - 1);
            int x1i = min(x0 + 1, W - 1);

            const unsigned long long base =
                (unsigned long long)fmap + (unsigned long long)b * H * W * CCH * 4ull;
            const unsigned long long rowT = base + (unsigned long long)(y0  * W) * (CCH * 4ull);
            const unsigned long long rowB = base + (unsigned long long)(y1i * W) * (CCH * 4ull);

            ulonglong4 a;
            a.x = rowT + (unsigned long long)x0  * (CCH * 4ull);
            a.y = rowT + (unsigned long long)x1i * (CCH * 4ull);
            a.z = rowB + (unsigned long long)x0  * (CCH * 4ull);
            a.w = rowB + (unsigned long long)x1i * (CCH * 4ull);
            s_addr[warp_in_cta][lane32] = a;
            s_w[warp_in_cta][lane32] = make_float2(wx, wy);
        }
    }
    __syncwarp();

    // ---- gather: half-warp g handles items wbase+g and wbase+g+2 ----
    const int g    = lane32 >> 4;          // 0 or 1
    const int lane = lane32 & (LANES - 1);

#pragma unroll
    for (int k = 0; k < 2; k++) {
        const int slot = g + 2 * k;
        const int item = wbase + slot;
        if (item >= total_items) break;

        const ulonglong4 a = s_addr[warp_in_cta][slot];
        const float2 wv = s_w[warp_in_cta][slot];
        const float wx = wv.x, wy = wv.y;

        const float4* __restrict__ tl = (const float4*)a.x;
        const float4* __restrict__ tr = (const float4*)a.y;
        const float4* __restrict__ bl = (const float4*)a.z;
        const float4* __restrict__ br = (const float4*)a.w;
        float4* __restrict__ o = (float4*)(out + (size_t)item * CCH);

#pragma unroll
        for (int j = 0; j < 4; j++) {
            const int c = lane + j * LANES;
            const float4 vtl = tl[c];
            const float4 vtr = tr[c];
            const float4 vbl = bl[c];
            const float4 vbr = br[c];
            float4 r;
            float t, bt;
            t  = vtl.x + (vtr.x - vtl.x) * wx;  bt = vbl.x + (vbr.x - vbl.x) * wx;  r.x = t + (bt - t) * wy;
            t  = vtl.y + (vtr.y - vtl.y) * wx;  bt = vbl.y + (vbr.y - vbl.y) * wx;  r.y = t + (bt - t) * wy;
            t  = vtl.z + (vtr.z - vtl.z) * wx;  bt = vbl.z + (vbr.z - vbl.z) * wx;  r.z = t + (bt - t) * wy;
            t  = vtl.w + (vtr.w - vtl.w) * wx;  bt = vbl.w + (vbr.w - vbl.w) * wx;  r.w = t + (bt - t) * wy;
            o[c] = r;
        }
    }
}

extern "C" void kernel_launch(void* const* d_in, const int* in_sizes, int n_in,
                              void* d_out, int out_size)
{
    const float* boxes = (const float*)d_in[0];
    const float* ishp  = (const float*)d_in[1];
    const float* P2    = (const float*)d_in[2];
    const float* P3    = (const float*)d_in[3];
    const float* P4    = (const float*)d_in[4];
    const float* P5    = (const float*)d_in[5];
    float* out = (float*)d_out;

    const int B = in_sizes[2] / (256 * 256 * 256);
    const int total_boxes = in_sizes[0] / 4;
    const int boxes_per_batch = total_boxes / B;
    const int total_items = total_boxes * NPTS;

    const int items_per_cta = WARPS_PER_CTA * ITEMS_PER_WARP;  // 32
    const int blocks = (total_items + items_per_cta - 1) / items_per_cta;
    roi_warpauto_kernel<<<blocks, 256>>>(boxes, ishp, P2, P3, P4, P5, out,
                                         total_items, boxes_per_batch);
}